// round 1
// baseline (speedup 1.0000x reference)
#include <cuda_runtime.h>

// IDWT layer: x(16, 32768, 64) -> out(16, 65536, 32)
//   approx = x[:,:,:32], detail = x[:,:,32:]
//   out = conv_same(up2(approx), rec_lo) + conv_same(up2(detail), rec_hi)
// With pad_lo=3, cross-correlation: out[n] = sum_k up[n-3+k]*f[k].
// up[2m]=x[m], up[odd]=0  =>
//   out[2t]   = sum_{i=0..3} a[t-1+i]*lo[2i+1] + d[t-1+i]*hi[2i+1]
//   out[2t+1] = sum_{i=0..3} a[t-1+i]*lo[2i]   + d[t-1+i]*hi[2i]
// Both outputs of a pair share the same 4 input rows.

#define T_TILE 128
#define ROWS   (T_TILE + 3)
#define THREADS 256
#define L_IN   32768
#define B_DIM  16

__global__ __launch_bounds__(THREADS)
void idwt_kernel(const float* __restrict__ x,
                 const float* __restrict__ lo,
                 const float* __restrict__ hi,
                 float* __restrict__ out)
{
    __shared__ float s[ROWS * 64];   // rows m = t0-1 .. t0+T_TILE+1, 64 ch each

    const int b  = blockIdx.y;
    const int t0 = blockIdx.x * T_TILE;
    const int tid = threadIdx.x;

    const float* xb = x + (size_t)b * L_IN * 64;

    // Stage input tile (float4, coalesced). ROWS*16 float4s total.
    #pragma unroll 4
    for (int i = tid; i < ROWS * 16; i += THREADS) {
        const int r = i >> 4;
        const int q = i & 15;
        const int m = t0 - 1 + r;
        float4 v = make_float4(0.f, 0.f, 0.f, 0.f);
        if (m >= 0 && m < L_IN)
            v = reinterpret_cast<const float4*>(xb + (size_t)m * 64)[q];
        reinterpret_cast<float4*>(s)[i] = v;
    }

    // Filter taps (broadcast loads, L1/const-cached)
    const float lo0 = lo[0], lo1 = lo[1], lo2 = lo[2], lo3 = lo[3];
    const float lo4 = lo[4], lo5 = lo[5], lo6 = lo[6], lo7 = lo[7];
    const float hi0 = hi[0], hi1 = hi[1], hi2 = hi[2], hi3 = hi[3];
    const float hi4 = hi[4], hi5 = hi[5], hi6 = hi[6], hi7 = hi[7];

    __syncthreads();

    float* ob = out + (size_t)b * 65536 * 32;

    const int c4  = tid & 7;    // float4 index within 32 channels (0..7)
    const int tl0 = tid >> 3;   // 0..31

    #pragma unroll
    for (int tl = tl0; tl < T_TILE; tl += 32) {
        // rows tl..tl+3 hold m = t-1 .. t+2 (t = t0+tl)
        const float4* base = reinterpret_cast<const float4*>(s) + c4;
        float4 a0 = base[(tl + 0) * 16];
        float4 a1 = base[(tl + 1) * 16];
        float4 a2 = base[(tl + 2) * 16];
        float4 a3 = base[(tl + 3) * 16];
        float4 d0 = base[(tl + 0) * 16 + 8];
        float4 d1 = base[(tl + 1) * 16 + 8];
        float4 d2 = base[(tl + 2) * 16 + 8];
        float4 d3 = base[(tl + 3) * 16 + 8];

        float4 ev, od;
        // even output: lo[1],lo[3],lo[5],lo[7] / hi[1],hi[3],hi[5],hi[7]
        ev.x = a0.x*lo1 + a1.x*lo3 + a2.x*lo5 + a3.x*lo7
             + d0.x*hi1 + d1.x*hi3 + d2.x*hi5 + d3.x*hi7;
        ev.y = a0.y*lo1 + a1.y*lo3 + a2.y*lo5 + a3.y*lo7
             + d0.y*hi1 + d1.y*hi3 + d2.y*hi5 + d3.y*hi7;
        ev.z = a0.z*lo1 + a1.z*lo3 + a2.z*lo5 + a3.z*lo7
             + d0.z*hi1 + d1.z*hi3 + d2.z*hi5 + d3.z*hi7;
        ev.w = a0.w*lo1 + a1.w*lo3 + a2.w*lo5 + a3.w*lo7
             + d0.w*hi1 + d1.w*hi3 + d2.w*hi5 + d3.w*hi7;
        // odd output: lo[0],lo[2],lo[4],lo[6] / hi even taps
        od.x = a0.x*lo0 + a1.x*lo2 + a2.x*lo4 + a3.x*lo6
             + d0.x*hi0 + d1.x*hi2 + d2.x*hi4 + d3.x*hi6;
        od.y = a0.y*lo0 + a1.y*lo2 + a2.y*lo4 + a3.y*lo6
             + d0.y*hi0 + d1.y*hi2 + d2.y*hi4 + d3.y*hi6;
        od.z = a0.z*lo0 + a1.z*lo2 + a2.z*lo4 + a3.z*lo6
             + d0.z*hi0 + d1.z*hi2 + d2.z*hi4 + d3.z*hi6;
        od.w = a0.w*lo0 + a1.w*lo2 + a2.w*lo4 + a3.w*lo6
             + d0.w*hi0 + d1.w*hi2 + d2.w*hi4 + d3.w*hi6;

        const size_t t = (size_t)(t0 + tl);
        float4* orow = reinterpret_cast<float4*>(ob + t * 64) + c4; // n=2t row base
        orow[0] = ev;       // out[2t,   c4*4 .. +3]
        orow[8] = od;       // out[2t+1, c4*4 .. +3]
    }
}

extern "C" void kernel_launch(void* const* d_in, const int* in_sizes, int n_in,
                              void* d_out, int out_size) {
    const float* x  = (const float*)d_in[0];
    const float* lo = (const float*)d_in[1];
    const float* hi = (const float*)d_in[2];
    float* out = (float*)d_out;

    dim3 grid(L_IN / T_TILE, B_DIM);
    idwt_kernel<<<grid, THREADS>>>(x, lo, hi, out);
}

// round 2
// speedup vs baseline: 1.2527x; 1.2527x over previous
#include <cuda_runtime.h>

// IDWT layer: x(16, 32768, 64) -> out(16, 65536, 32)
//   approx = x[:,:,:32], detail = x[:,:,32:]
//   out[2t]   = sum_{i=0..3} a[t-1+i]*lo[2i+1] + d[t-1+i]*hi[2i+1]
//   out[2t+1] = sum_{i=0..3} a[t-1+i]*lo[2i]   + d[t-1+i]*hi[2i]
//
// Register-rolling strip kernel, no shared memory:
// each thread owns one float4 channel-lane (c4 in 0..7) of a strip of
// T_STRIP=8 consecutive t values. It loads rows t0-1 .. t0+9 (11 rows,
// 22 independent LDG.128 -> high MLP), then emits 16 float4 stores.
// Halo read amplification (T+3)/T = 1.375x is absorbed by L2 (shared
// with adjacent strips). Streaming stores keep writes from thrashing L2.

#define T_STRIP 8
#define NROWS   (T_STRIP + 3)     // 11
#define THREADS 256
#define L_IN    32768
#define B_DIM   16

__device__ __forceinline__ void stcs4(float4* p, float4 v) {
    asm volatile("st.global.cs.v4.f32 [%0], {%1,%2,%3,%4};"
                 :: "l"(p), "f"(v.x), "f"(v.y), "f"(v.z), "f"(v.w) : "memory");
}

__global__ __launch_bounds__(THREADS)
void idwt_kernel(const float* __restrict__ x,
                 const float* __restrict__ lo,
                 const float* __restrict__ hi,
                 float* __restrict__ out)
{
    const int tid  = threadIdx.x;
    const int c4   = tid & 7;                        // float4 index within 32 ch
    const int sidx = tid >> 3;                       // strip within block (0..31)
    const int b    = blockIdx.y;
    const int t0   = (blockIdx.x * 32 + sidx) * T_STRIP;

    const float* xb = x + (size_t)b * L_IN * 64;

    // ---- load 11 rows x {approx, detail} float4, fully batched ----
    float4 a[NROWS], d[NROWS];
    const float4* p = reinterpret_cast<const float4*>(xb) + (size_t)(t0 - 1) * 16 + c4;
    const float4 z = make_float4(0.f, 0.f, 0.f, 0.f);

    if (t0 >= 1 && t0 + NROWS - 2 < L_IN) {          // interior fast path
        #pragma unroll
        for (int r = 0; r < NROWS; r++) {
            a[r] = p[r * 16];
            d[r] = p[r * 16 + 8];
        }
    } else {                                          // batch edges: predicate
        #pragma unroll
        for (int r = 0; r < NROWS; r++) {
            const int m = t0 - 1 + r;
            const bool ok = (m >= 0) && (m < L_IN);
            a[r] = ok ? p[r * 16]     : z;
            d[r] = ok ? p[r * 16 + 8] : z;
        }
    }

    const float lo0 = lo[0], lo1 = lo[1], lo2 = lo[2], lo3 = lo[3];
    const float lo4 = lo[4], lo5 = lo[5], lo6 = lo[6], lo7 = lo[7];
    const float hi0 = hi[0], hi1 = hi[1], hi2 = hi[2], hi3 = hi[3];
    const float hi4 = hi[4], hi5 = hi[5], hi6 = hi[6], hi7 = hi[7];

    float4* ob = reinterpret_cast<float4*>(out + (size_t)b * 65536 * 32);

    #pragma unroll
    for (int tl = 0; tl < T_STRIP; tl++) {
        const float4 a0 = a[tl], a1 = a[tl + 1], a2 = a[tl + 2], a3 = a[tl + 3];
        const float4 d0 = d[tl], d1 = d[tl + 1], d2 = d[tl + 2], d3 = d[tl + 3];

        float4 ev, od;
        ev.x = a0.x*lo1 + a1.x*lo3 + a2.x*lo5 + a3.x*lo7
             + d0.x*hi1 + d1.x*hi3 + d2.x*hi5 + d3.x*hi7;
        ev.y = a0.y*lo1 + a1.y*lo3 + a2.y*lo5 + a3.y*lo7
             + d0.y*hi1 + d1.y*hi3 + d2.y*hi5 + d3.y*hi7;
        ev.z = a0.z*lo1 + a1.z*lo3 + a2.z*lo5 + a3.z*lo7
             + d0.z*hi1 + d1.z*hi3 + d2.z*hi5 + d3.z*hi7;
        ev.w = a0.w*lo1 + a1.w*lo3 + a2.w*lo5 + a3.w*lo7
             + d0.w*hi1 + d1.w*hi3 + d2.w*hi5 + d3.w*hi7;

        od.x = a0.x*lo0 + a1.x*lo2 + a2.x*lo4 + a3.x*lo6
             + d0.x*hi0 + d1.x*hi2 + d2.x*hi4 + d3.x*hi6;
        od.y = a0.y*lo0 + a1.y*lo2 + a2.y*lo4 + a3.y*lo6
             + d0.y*hi0 + d1.y*hi2 + d2.y*hi4 + d3.y*hi6;
        od.z = a0.z*lo0 + a1.z*lo2 + a2.z*lo4 + a3.z*lo6
             + d0.z*hi0 + d1.z*hi2 + d2.z*hi4 + d3.z*hi6;
        od.w = a0.w*lo0 + a1.w*lo2 + a2.w*lo4 + a3.w*lo6
             + d0.w*hi0 + d1.w*hi2 + d2.w*hi4 + d3.w*hi6;

        const size_t t = (size_t)(t0 + tl);
        float4* orow = ob + t * 16 + c4;   // out row n=2t starts at t*64 floats
        stcs4(orow,     ev);               // out[2t]
        stcs4(orow + 8, od);               // out[2t+1]
    }
}

extern "C" void kernel_launch(void* const* d_in, const int* in_sizes, int n_in,
                              void* d_out, int out_size) {
    const float* x  = (const float*)d_in[0];
    const float* lo = (const float*)d_in[1];
    const float* hi = (const float*)d_in[2];
    float* out = (float*)d_out;

    // strips per batch = 32768/8 = 4096; 32 strips per 256-thread block
    dim3 grid(L_IN / T_STRIP / 32, B_DIM);
    idwt_kernel<<<grid, THREADS>>>(x, lo, hi, out);
}